// round 7
// baseline (speedup 1.0000x reference)
#include <cuda_runtime.h>
#include <cuda_bf16.h>

// Problem constants (HiePoolingLayer): nn_outs (B,T,E) f32, batch_x (B,T) int
#define B 32
#define T 4096
#define E 256
#define E4 (E / 4)   // 64 float4 lanes per token row

// __device__ scratch (no dynamic allocation allowed)
__device__ int g_cut_pos[B][T];   // token index of k-th cut in row b
__device__ int g_ncuts[B];        // number of cuts (segments) in row b

// ---------------------------------------------------------------------------
// Kernel 1 (fused prep): per-row dtype detection + cut scan + ncuts + tail.
// One block per row, 256 threads x 16 words each (loaded as 4x int4).
//
// Layout detection (per-block, globally consistent):
//  - int32 layout: cuts sit at odd word indices -> some odd word nonzero.
//  - int64 layout: odd words are hi-halves of 0/1 values -> all zero.
// ---------------------------------------------------------------------------
__global__ __launch_bounds__(256) void prep_kernel(const int* __restrict__ bx32,
                                                   float* __restrict__ out,
                                                   long long tail_off,
                                                   int tail_mode) {
    const int b    = blockIdx.x;
    const int tid  = threadIdx.x;
    const int base = tid * 16;

    // vectorized load: 16 words = 4 x int4, 4 independent LDG.128
    int v[16];
    const int4* slice4 = (const int4*)(bx32 + (size_t)b * T) + tid * 4;
    int4 w0 = slice4[0], w1 = slice4[1], w2 = slice4[2], w3 = slice4[3];
    v[0]=w0.x; v[1]=w0.y; v[2]=w0.z; v[3]=w0.w;
    v[4]=w1.x; v[5]=w1.y; v[6]=w1.z; v[7]=w1.w;
    v[8]=w2.x; v[9]=w2.y; v[10]=w2.z; v[11]=w2.w;
    v[12]=w3.x; v[13]=w3.y; v[14]=w3.z; v[15]=w3.w;

    int odd_any = 0;
#pragma unroll
    for (int i = 1; i < 16; i += 2) odd_any |= v[i];
    const int is32 = __syncthreads_or(odd_any != 0);

    unsigned mask = 0;
    int cnt = 0;
    if (is32) {
#pragma unroll
        for (int i = 0; i < 16; i++) {
            if (v[i] == 1) { mask |= (1u << i); cnt++; }
        }
    } else {
        // int64 layout: token j occupies words (2j, 2j+1). My 16 words cover
        // tokens [base/2, base/2+8): value==1 <=> lo==1 && hi==0.
        // Re-derive from the already-loaded words (tokens tid*8 .. tid*8+7),
        // then rescan at the proper granularity: each thread owns 8 tokens.
#pragma unroll
        for (int i = 0; i < 8; i++) {
            if (v[2 * i] == 1 && v[2 * i + 1] == 0) {
                mask |= (1u << i); cnt++;
            }
        }
    }

    // warp inclusive scan of cnt
    const int lane = tid & 31;
    const int wid  = tid >> 5;
    int x = cnt;
#pragma unroll
    for (int o = 1; o < 32; o <<= 1) {
        int y = __shfl_up_sync(0xFFFFFFFFu, x, o);
        if (lane >= o) x += y;
    }

    __shared__ int wsum[8];
    if (lane == 31) wsum[wid] = x;
    __syncthreads();

    int wexcl = 0;
    for (int i = 0; i < wid; i++) wexcl += wsum[i];

    const int excl = wexcl + x - cnt;   // rank of my first cut

    // token index base differs by layout: i32 -> 16 tokens/thread at tid*16,
    // i64 -> 8 tokens/thread at tid*8.
    const int tok_base = is32 ? base : tid * 8;
    int r = excl;
#pragma unroll
    for (int i = 0; i < 16; i++) {
        if ((mask >> i) & 1u) {
            g_cut_pos[b][r++] = tok_base + i;
        }
    }

    if (tid == blockDim.x - 1) {
        const int total = excl + cnt;
        g_ncuts[b] = total;
        if (tail_mode == 1) {
            out[tail_off + b] = (float)total;           // f32 output dtype
        } else if (tail_mode == 2) {
            ((long long*)out)[tail_off / 2 + b] = (long long)total;  // i64
        }
    }
}

// ---------------------------------------------------------------------------
// Kernel 2: pool. 64-thread blocks, forced 32 blocks/SM (regs capped at 32),
// persistent grid-stride over segments. Streaming loads/stores (__ldcs/__stcs)
// since all data is use-once. PDL overlaps rollout with prep.
// ---------------------------------------------------------------------------
__global__ __launch_bounds__(E4, 32) void pool_kernel(const float* __restrict__ nn,
                                                      float* __restrict__ out,
                                                      int maxlen) {
    cudaGridDependencySynchronize();

    const int nseg = B * maxlen;
    const int tid  = threadIdx.x;

    for (int flat = blockIdx.x; flat < nseg; flat += gridDim.x) {
        const int b   = flat / maxlen;
        const int seg = flat % maxlen;

        float4* o = (float4*)out + (size_t)flat * E4 + tid;

        const int nc = g_ncuts[b];
        if (seg >= nc) {
            __stcs(o, make_float4(0.f, 0.f, 0.f, 0.f));  // pad -> zeros
            continue;
        }

        const int end   = g_cut_pos[b][seg];                     // inclusive
        const int start = (seg > 0) ? (g_cut_pos[b][seg - 1] + 1) : 0;
        const int len   = end - start + 1;

        const float4* src = (const float4*)(nn + ((size_t)b * T + start) * E) + tid;

        float4 acc = make_float4(0.f, 0.f, 0.f, 0.f);
#pragma unroll 4
        for (int t = 0; t < len; t++) {
            float4 v = __ldcs(src + (size_t)t * E4);
            acc.x += v.x; acc.y += v.y; acc.z += v.z; acc.w += v.w;
        }

        const float inv = 1.0f / (float)len;
        acc.x *= inv; acc.y *= inv; acc.z *= inv; acc.w *= inv;
        __stcs(o, acc);
    }
}

extern "C" void kernel_launch(void* const* d_in, const int* in_sizes, int n_in,
                              void* d_out, int out_size) {
    // Defensive input-order check: nn_outs has B*T*E elements, batch_x B*T.
    int i_nn = 0, i_bx = 1;
    if (n_in >= 2 && in_sizes[0] == B * T && in_sizes[1] != B * T) {
        i_nn = 1; i_bx = 0;
    }
    const float* nn   = (const float*)d_in[i_nn];    // (B,T,E) f32
    const int*   bx32 = (const int*)d_in[i_bx];      // (B,T) i32 or i64 view
    float*       out  = (float*)d_out;

    // Derive maxlen (and optional n_cuts tail) from out_size.
    const long long bE = (long long)B * E;
    int maxlen = 0;
    int tail_mode = 0;  // 0=none, 1=B output-dtype elems (float), 2=i64 tail
    if (out_size % bE == 0) {
        maxlen = (int)(out_size / bE);
    } else if ((out_size - B) % bE == 0) {
        maxlen = (int)((out_size - B) / bE);
        tail_mode = 1;
    } else if ((out_size - 2 * B) % bE == 0) {
        maxlen = (int)((out_size - 2 * B) / bE);
        tail_mode = 2;
    } else {
        maxlen = T / 16;  // fallback: uniform stride-16 cuts
    }

    const long long tail_off = (long long)B * maxlen * E;

    prep_kernel<<<B, 256>>>(bx32, out, tail_off, tail_mode);

    // Persistent single-wave grid: 148 SMs x 32 blocks of 64 threads.
    int nseg    = B * maxlen;
    int nblocks = 148 * 32;
    if (nblocks > nseg) nblocks = nseg;

    // PDL launch: overlap pool's block rollout with prep's tail.
    cudaLaunchConfig_t cfg = {};
    cfg.gridDim  = dim3((unsigned)nblocks, 1, 1);
    cfg.blockDim = dim3(E4, 1, 1);
    cfg.dynamicSmemBytes = 0;
    cfg.stream = 0;
    cudaLaunchAttribute attrs[1];
    attrs[0].id = cudaLaunchAttributeProgrammaticStreamSerialization;
    attrs[0].val.programmaticStreamSerializationAllowed = 1;
    cfg.attrs = attrs;
    cfg.numAttrs = 1;
    cudaError_t err = cudaLaunchKernelEx(&cfg, pool_kernel, nn, out, maxlen);
    if (err != cudaSuccess) {
        // Fallback: plain launch (still correct, just serialized).
        pool_kernel<<<nblocks, E4>>>(nn, out, maxlen);
    }
}

// round 8
// speedup vs baseline: 1.0598x; 1.0598x over previous
#include <cuda_runtime.h>
#include <cuda_bf16.h>

// Problem constants (HiePoolingLayer): nn_outs (B,T,E) f32, batch_x (B,T) int
#define B 32
#define T 4096
#define E 256
#define E4 (E / 4)   // 64 float4 lanes per token row

// __device__ scratch (no dynamic allocation allowed)
__device__ int g_cut_pos[B][T];     // token index of k-th cut in row b
__device__ int g_ncuts[B];          // number of cuts (segments) in row b
__device__ int g_row_uniform[B];    // 1 if row's cuts are exactly 15,31,...

// ---------------------------------------------------------------------------
// Kernel 1 (fused prep): dtype detect + cut scan + ncuts + uniform flag + tail.
// One block per row, 256 threads x 16 tokens each.
// Detection (globally consistent): int32 layout has cuts at odd word indices;
// int64 layout's odd words (hi halves of 0/1) are all zero.
// ---------------------------------------------------------------------------
__global__ __launch_bounds__(256) void prep_kernel(const int* __restrict__ bx32,
                                                   float* __restrict__ out,
                                                   long long tail_off,
                                                   int tail_mode) {
    const int b    = blockIdx.x;
    const int tid  = threadIdx.x;
    const int base = tid * 16;

    // vectorized probe load: 16 words at [b*T + tid*16] (4 x LDG.128)
    int v[16];
    const int4* slice4 = (const int4*)(bx32 + (size_t)b * T) + tid * 4;
    int4 w0 = slice4[0], w1 = slice4[1], w2 = slice4[2], w3 = slice4[3];
    v[0]=w0.x; v[1]=w0.y; v[2]=w0.z; v[3]=w0.w;
    v[4]=w1.x; v[5]=w1.y; v[6]=w1.z; v[7]=w1.w;
    v[8]=w2.x; v[9]=w2.y; v[10]=w2.z; v[11]=w2.w;
    v[12]=w3.x; v[13]=w3.y; v[14]=w3.z; v[15]=w3.w;

    int odd_any = 0;
#pragma unroll
    for (int i = 1; i < 16; i += 2) odd_any |= v[i];
    const int is32 = __syncthreads_or(odd_any != 0);

    // build cut mask for my 16 tokens (base .. base+15)
    unsigned mask = 0;
    int cnt = 0;
    if (is32) {
        // probe words ARE this row's tokens
#pragma unroll
        for (int i = 0; i < 16; i++) {
            if (v[i] == 1) { mask |= (1u << i); cnt++; }
        }
    } else {
        // int64 layout: row b at words [b*2T, b*2T+2T); token j = words 2j,2j+1
        const int* row64 = bx32 + (size_t)b * T * 2;
#pragma unroll
        for (int i = 0; i < 16; i++) {
            if (row64[2 * (base + i)] == 1 && row64[2 * (base + i) + 1] == 0) {
                mask |= (1u << i); cnt++;
            }
        }
    }

    // uniform-row detection: every 16-token chunk has exactly one cut at
    // local offset 15  (global positions 15, 31, ..., stride 16)
    const int uniform = __syncthreads_and(mask == 0x8000u);

    // warp inclusive scan of cnt
    const int lane = tid & 31;
    const int wid  = tid >> 5;
    int x = cnt;
#pragma unroll
    for (int o = 1; o < 32; o <<= 1) {
        int y = __shfl_up_sync(0xFFFFFFFFu, x, o);
        if (lane >= o) x += y;
    }

    __shared__ int wsum[8];
    if (lane == 31) wsum[wid] = x;
    __syncthreads();

    int wexcl = 0;
    for (int i = 0; i < wid; i++) wexcl += wsum[i];

    const int excl = wexcl + x - cnt;   // rank of my first cut

    int r = excl;
#pragma unroll
    for (int i = 0; i < 16; i++) {
        if ((mask >> i) & 1u) {
            g_cut_pos[b][r++] = base + i;
        }
    }

    if (tid == blockDim.x - 1) {
        const int total = excl + cnt;
        g_ncuts[b] = total;
        g_row_uniform[b] = uniform;     // unconditional write: replay-safe
        if (tail_mode == 1) {
            out[tail_off + b] = (float)total;           // f32 output dtype
        } else if (tail_mode == 2) {
            ((long long*)out)[tail_off / 2 + b] = (long long)total;  // i64
        }
    }
}

// ---------------------------------------------------------------------------
// Kernel 2: pool. 64-thread blocks, persistent grid-stride over segments,
// PDL overlapped with prep. Uniform rows take a compile-time len=16 fully
// unrolled path (16 front-batched LDG.128, no cut_pos loads).
// ---------------------------------------------------------------------------
__global__ __launch_bounds__(E4) void pool_kernel(const float* __restrict__ nn,
                                                  float* __restrict__ out,
                                                  int maxlen) {
    cudaGridDependencySynchronize();

    const int nseg = B * maxlen;
    const int tid  = threadIdx.x;

    for (int flat = blockIdx.x; flat < nseg; flat += gridDim.x) {
        const int b   = flat / maxlen;
        const int seg = flat % maxlen;

        float4* o = (float4*)out + (size_t)flat * E4 + tid;

        const int nc = g_ncuts[b];
        if (seg >= nc) {
            *o = make_float4(0.f, 0.f, 0.f, 0.f);   // pad segment -> zeros
            continue;
        }

        if (g_row_uniform[b]) {
            // fast path: segment = tokens [seg*16, seg*16+15], len = 16
            const int start = seg << 4;
            const float4* src =
                (const float4*)nn + ((size_t)b * T + start) * E4 + tid;
            float4 acc = make_float4(0.f, 0.f, 0.f, 0.f);
#pragma unroll
            for (int t = 0; t < 16; t++) {
                float4 v = src[(size_t)t * E4];
                acc.x += v.x; acc.y += v.y; acc.z += v.z; acc.w += v.w;
            }
            acc.x *= 0.0625f; acc.y *= 0.0625f;
            acc.z *= 0.0625f; acc.w *= 0.0625f;
            *o = acc;
        } else {
            // generic path: arbitrary cut positions
            const int end   = g_cut_pos[b][seg];                   // inclusive
            const int start = (seg > 0) ? (g_cut_pos[b][seg - 1] + 1) : 0;
            const int len   = end - start + 1;

            const float4* src =
                (const float4*)nn + ((size_t)b * T + start) * E4 + tid;
            float4 acc = make_float4(0.f, 0.f, 0.f, 0.f);
#pragma unroll 4
            for (int t = 0; t < len; t++) {
                float4 v = src[(size_t)t * E4];
                acc.x += v.x; acc.y += v.y; acc.z += v.z; acc.w += v.w;
            }
            const float inv = 1.0f / (float)len;
            acc.x *= inv; acc.y *= inv; acc.z *= inv; acc.w *= inv;
            *o = acc;
        }
    }
}

extern "C" void kernel_launch(void* const* d_in, const int* in_sizes, int n_in,
                              void* d_out, int out_size) {
    // Defensive input-order check: nn_outs has B*T*E elements, batch_x B*T.
    int i_nn = 0, i_bx = 1;
    if (n_in >= 2 && in_sizes[0] == B * T && in_sizes[1] != B * T) {
        i_nn = 1; i_bx = 0;
    }
    const float* nn   = (const float*)d_in[i_nn];    // (B,T,E) f32
    const int*   bx32 = (const int*)d_in[i_bx];      // (B,T) i32 or i64 view
    float*       out  = (float*)d_out;

    // Derive maxlen (and optional n_cuts tail) from out_size.
    const long long bE = (long long)B * E;
    int maxlen = 0;
    int tail_mode = 0;  // 0=none, 1=B output-dtype elems (float), 2=i64 tail
    if (out_size % bE == 0) {
        maxlen = (int)(out_size / bE);
    } else if ((out_size - B) % bE == 0) {
        maxlen = (int)((out_size - B) / bE);
        tail_mode = 1;
    } else if ((out_size - 2 * B) % bE == 0) {
        maxlen = (int)((out_size - 2 * B) / bE);
        tail_mode = 2;
    } else {
        maxlen = T / 16;  // fallback: uniform stride-16 cuts
    }

    const long long tail_off = (long long)B * maxlen * E;

    prep_kernel<<<B, 256>>>(bx32, out, tail_off, tail_mode);

    // Persistent single-wave grid: 148 SMs x 32 blocks of 64 threads.
    int nseg    = B * maxlen;
    int nblocks = 148 * 32;
    if (nblocks > nseg) nblocks = nseg;

    // PDL launch: overlap pool's block rollout with prep.
    cudaLaunchConfig_t cfg = {};
    cfg.gridDim  = dim3((unsigned)nblocks, 1, 1);
    cfg.blockDim = dim3(E4, 1, 1);
    cfg.dynamicSmemBytes = 0;
    cfg.stream = 0;
    cudaLaunchAttribute attrs[1];
    attrs[0].id = cudaLaunchAttributeProgrammaticStreamSerialization;
    attrs[0].val.programmaticStreamSerializationAllowed = 1;
    cfg.attrs = attrs;
    cfg.numAttrs = 1;
    cudaError_t err = cudaLaunchKernelEx(&cfg, pool_kernel, nn, out, maxlen);
    if (err != cudaSuccess) {
        // Fallback: plain launch (still correct, just serialized).
        pool_kernel<<<nblocks, E4>>>(nn, out, maxlen);
    }
}

// round 9
// speedup vs baseline: 1.0703x; 1.0099x over previous
#include <cuda_runtime.h>
#include <cuda_bf16.h>

// Problem constants (HiePoolingLayer): nn_outs (B,T,E) f32, batch_x (B,T) int
#define B 32
#define T 4096
#define E 256
#define E4 (E / 4)   // 64 float4 lanes per token row

// __device__ scratch (no dynamic allocation allowed)
__device__ int g_cut_pos[B][T];     // token index of k-th cut in row b
__device__ int g_ncuts[B];          // number of cuts (segments) in row b
__device__ int g_row_uniform[B];    // 1 if row's cuts are exactly 15,31,...

// ---------------------------------------------------------------------------
// Kernel 1 (fused prep): dtype detect + cut scan + ncuts + uniform flag + tail.
// One block per row, 256 threads x 16 tokens each.
// Detection (globally consistent): int32 layout has cuts at odd word indices;
// int64 layout's odd words (hi halves of 0/1) are all zero.
// ---------------------------------------------------------------------------
__global__ __launch_bounds__(256) void prep_kernel(const int* __restrict__ bx32,
                                                   float* __restrict__ out,
                                                   long long tail_off,
                                                   int tail_mode) {
    const int b    = blockIdx.x;
    const int tid  = threadIdx.x;
    const int base = tid * 16;

    // vectorized probe load: 16 words at [b*T + tid*16] (4 x LDG.128)
    int v[16];
    const int4* slice4 = (const int4*)(bx32 + (size_t)b * T) + tid * 4;
    int4 w0 = slice4[0], w1 = slice4[1], w2 = slice4[2], w3 = slice4[3];
    v[0]=w0.x; v[1]=w0.y; v[2]=w0.z; v[3]=w0.w;
    v[4]=w1.x; v[5]=w1.y; v[6]=w1.z; v[7]=w1.w;
    v[8]=w2.x; v[9]=w2.y; v[10]=w2.z; v[11]=w2.w;
    v[12]=w3.x; v[13]=w3.y; v[14]=w3.z; v[15]=w3.w;

    int odd_any = 0;
#pragma unroll
    for (int i = 1; i < 16; i += 2) odd_any |= v[i];
    const int is32 = __syncthreads_or(odd_any != 0);

    // build cut mask for my 16 tokens (base .. base+15)
    unsigned mask = 0;
    int cnt = 0;
    if (is32) {
#pragma unroll
        for (int i = 0; i < 16; i++) {
            if (v[i] == 1) { mask |= (1u << i); cnt++; }
        }
    } else {
        // int64 layout: row b at words [b*2T, b*2T+2T); token j = words 2j,2j+1
        const int* row64 = bx32 + (size_t)b * T * 2;
#pragma unroll
        for (int i = 0; i < 16; i++) {
            if (row64[2 * (base + i)] == 1 && row64[2 * (base + i) + 1] == 0) {
                mask |= (1u << i); cnt++;
            }
        }
    }

    // uniform-row detection: every 16-token chunk has exactly one cut at
    // local offset 15 (global cut positions 15, 31, ..., stride 16)
    const int uniform = __syncthreads_and(mask == 0x8000u);

    // warp inclusive scan of cnt
    const int lane = tid & 31;
    const int wid  = tid >> 5;
    int x = cnt;
#pragma unroll
    for (int o = 1; o < 32; o <<= 1) {
        int y = __shfl_up_sync(0xFFFFFFFFu, x, o);
        if (lane >= o) x += y;
    }

    __shared__ int wsum[8];
    if (lane == 31) wsum[wid] = x;
    __syncthreads();

    int wexcl = 0;
    for (int i = 0; i < wid; i++) wexcl += wsum[i];

    const int excl = wexcl + x - cnt;   // rank of my first cut

    int r = excl;
#pragma unroll
    for (int i = 0; i < 16; i++) {
        if ((mask >> i) & 1u) {
            g_cut_pos[b][r++] = base + i;
        }
    }

    if (tid == blockDim.x - 1) {
        const int total = excl + cnt;
        g_ncuts[b] = total;
        g_row_uniform[b] = uniform;     // unconditional write: replay-safe
        if (tail_mode == 1) {
            out[tail_off + b] = (float)total;           // f32 output dtype
        } else if (tail_mode == 2) {
            ((long long*)out)[tail_off / 2 + b] = (long long)total;  // i64
        }
    }
}

// ---------------------------------------------------------------------------
// Kernel 2: pool. 64-thread blocks, persistent grid-stride over segments.
// PDL + SPECULATION: before waiting on prep, each block speculatively sums
// its first segment assuming the uniform stride-16 layout (loads of nn are
// always safe). After cudaGridDependencySynchronize(), the speculation is
// committed iff g_row_uniform[b]; otherwise the generic path recomputes.
// ---------------------------------------------------------------------------
__global__ __launch_bounds__(E4) void pool_kernel(const float* __restrict__ nn,
                                                  float* __restrict__ out,
                                                  int maxlen) {
    const int nseg = B * maxlen;
    const int tid  = threadIdx.x;

    // ---- speculative first iteration (overlaps prep execution) ----
    const int flat0 = blockIdx.x;
    float4 spec = make_float4(0.f, 0.f, 0.f, 0.f);
    int b0 = 0, seg0 = 0, can_spec = 0;
    if (flat0 < nseg) {
        b0   = flat0 / maxlen;
        seg0 = flat0 % maxlen;
        if (seg0 < T / 16) {
            can_spec = 1;
            const float4* src =
                (const float4*)nn + ((size_t)b0 * T + (seg0 << 4)) * E4 + tid;
#pragma unroll
            for (int t = 0; t < 16; t++) {
                float4 v = src[(size_t)t * E4];
                spec.x += v.x; spec.y += v.y; spec.z += v.z; spec.w += v.w;
            }
            spec.x *= 0.0625f; spec.y *= 0.0625f;
            spec.z *= 0.0625f; spec.w *= 0.0625f;
        }
    }

    cudaGridDependencySynchronize();   // prep results now visible

    int first = 1;
    for (int flat = flat0; flat < nseg; flat += gridDim.x) {
        const int b   = first ? b0   : flat / maxlen;
        const int seg = first ? seg0 : flat % maxlen;

        float4* o = (float4*)out + (size_t)flat * E4 + tid;

        if (first && can_spec && g_row_uniform[b] && seg < g_ncuts[b]) {
            *o = spec;                  // commit speculation
            first = 0;
            continue;
        }
        first = 0;

        const int nc = g_ncuts[b];
        if (seg >= nc) {
            *o = make_float4(0.f, 0.f, 0.f, 0.f);   // pad segment -> zeros
            continue;
        }

        if (g_row_uniform[b]) {
            // fast path: segment = tokens [seg*16, seg*16+15], len = 16
            const float4* src =
                (const float4*)nn + ((size_t)b * T + (seg << 4)) * E4 + tid;
            float4 acc = make_float4(0.f, 0.f, 0.f, 0.f);
#pragma unroll
            for (int t = 0; t < 16; t++) {
                float4 v = src[(size_t)t * E4];
                acc.x += v.x; acc.y += v.y; acc.z += v.z; acc.w += v.w;
            }
            acc.x *= 0.0625f; acc.y *= 0.0625f;
            acc.z *= 0.0625f; acc.w *= 0.0625f;
            *o = acc;
        } else {
            // generic path: arbitrary cut positions
            const int end   = g_cut_pos[b][seg];                   // inclusive
            const int start = (seg > 0) ? (g_cut_pos[b][seg - 1] + 1) : 0;
            const int len   = end - start + 1;

            const float4* src =
                (const float4*)nn + ((size_t)b * T + start) * E4 + tid;
            float4 acc = make_float4(0.f, 0.f, 0.f, 0.f);
#pragma unroll 4
            for (int t = 0; t < len; t++) {
                float4 v = src[(size_t)t * E4];
                acc.x += v.x; acc.y += v.y; acc.z += v.z; acc.w += v.w;
            }
            const float inv = 1.0f / (float)len;
            acc.x *= inv; acc.y *= inv; acc.z *= inv; acc.w *= inv;
            *o = acc;
        }
    }
}

extern "C" void kernel_launch(void* const* d_in, const int* in_sizes, int n_in,
                              void* d_out, int out_size) {
    // Defensive input-order check: nn_outs has B*T*E elements, batch_x B*T.
    int i_nn = 0, i_bx = 1;
    if (n_in >= 2 && in_sizes[0] == B * T && in_sizes[1] != B * T) {
        i_nn = 1; i_bx = 0;
    }
    const float* nn   = (const float*)d_in[i_nn];    // (B,T,E) f32
    const int*   bx32 = (const int*)d_in[i_bx];      // (B,T) i32 or i64 view
    float*       out  = (float*)d_out;

    // Derive maxlen (and optional n_cuts tail) from out_size.
    const long long bE = (long long)B * E;
    int maxlen = 0;
    int tail_mode = 0;  // 0=none, 1=B output-dtype elems (float), 2=i64 tail
    if (out_size % bE == 0) {
        maxlen = (int)(out_size / bE);
    } else if ((out_size - B) % bE == 0) {
        maxlen = (int)((out_size - B) / bE);
        tail_mode = 1;
    } else if ((out_size - 2 * B) % bE == 0) {
        maxlen = (int)((out_size - 2 * B) / bE);
        tail_mode = 2;
    } else {
        maxlen = T / 16;  // fallback: uniform stride-16 cuts
    }

    const long long tail_off = (long long)B * maxlen * E;

    prep_kernel<<<B, 256>>>(bx32, out, tail_off, tail_mode);

    // Persistent single-wave grid: 148 SMs x 32 blocks of 64 threads.
    int nseg    = B * maxlen;
    int nblocks = 148 * 32;
    if (nblocks > nseg) nblocks = nseg;

    // PDL launch: pool blocks roll out and run speculative loads during prep.
    cudaLaunchConfig_t cfg = {};
    cfg.gridDim  = dim3((unsigned)nblocks, 1, 1);
    cfg.blockDim = dim3(E4, 1, 1);
    cfg.dynamicSmemBytes = 0;
    cfg.stream = 0;
    cudaLaunchAttribute attrs[1];
    attrs[0].id = cudaLaunchAttributeProgrammaticStreamSerialization;
    attrs[0].val.programmaticStreamSerializationAllowed = 1;
    cfg.attrs = attrs;
    cfg.numAttrs = 1;
    cudaError_t err = cudaLaunchKernelEx(&cfg, pool_kernel, nn, out, maxlen);
    if (err != cudaSuccess) {
        // Fallback: plain launch (still correct, just serialized).
        pool_kernel<<<nblocks, E4>>>(nn, out, maxlen);
    }
}